// round 14
// baseline (speedup 1.0000x reference)
#include <cuda_runtime.h>
#include <cuda_fp16.h>
#include <cstdint>

#define N_NODES 100000
#define E_MAX   800000
#define F_IN 128
#define F_H  256
#define BN_EPS 1e-5f
#define L2_EPS 1e-12f

// ---------------- scratch (device globals; referenced ONLY from device code) --
__device__ __align__(16) uint32_t g_h1h[(size_t)N_NODES * 128];  // h1 fp16 packed
__device__ __align__(16) uint32_t g_xh [(size_t)N_NODES * 64];   // x  fp16 packed
__device__ int   g_cnt[N_NODES];
__device__ int   g_cur[N_NODES];
__device__ int   g_rowptr[N_NODES + 1];
__device__ int   g_bsum[128];
__device__ int   g_esrc[E_MAX];
__device__ int   g_is64;

// weights transposed fp16: B[n][k], n = out col (256), k = in
__device__ __align__(16) __half g_B1[256 * 256];
__device__ __align__(16) __half g_B2[256 * 512];

// ---------------- helpers ----------------
__device__ __forceinline__ uint32_t pack_f16(float x, float y) {
    __half2 h = __floats2half2_rn(x, y);
    return *(uint32_t*)&h;
}

__device__ __forceinline__ int edge_at(const void* ei, size_t i) {
    if (g_is64) return (int)((const long long*)ei)[i];
    return ((const int*)ei)[i];
}

// ---------------- setup: detect dtype + zero counters + weight/x fp16 --------
__global__ void setup_kernel(const int* __restrict__ ei_raw,
                             const float* __restrict__ W1_l, const float* __restrict__ W1_r,
                             const float* __restrict__ W2_l, const float* __restrict__ W2_r,
                             const float* __restrict__ x, int n_nodes) {
    // dtype detect (block 0 only)
    if (blockIdx.x == 0) {
        __shared__ int any_nonzero;
        if (threadIdx.x == 0) any_nonzero = 0;
        __syncthreads();
        if (threadIdx.x < 128) {
            int w = ei_raw[threadIdx.x * 2 + 1];
            if (w != 0) atomicOr(&any_nonzero, 1);
        }
        __syncthreads();
        if (threadIdx.x == 0) g_is64 = any_nonzero ? 0 : 1;
    }
    int tid = blockIdx.x * blockDim.x + threadIdx.x;
    int nthr = gridDim.x * blockDim.x;
    for (int i = tid; i < n_nodes; i += nthr) { g_cnt[i] = 0; g_cur[i] = 0; }
    for (int i = tid; i < 256 * 256; i += nthr) {
        int n = i >> 8, k = i & 255;
        float w = (k < 128) ? W1_l[k * 256 + n] : W1_r[(k - 128) * 256 + n];
        g_B1[i] = __float2half_rn(w);
    }
    for (int i = tid; i < 256 * 512; i += nthr) {
        int n = i >> 9, k = i & 511;
        float w = (k < 256) ? W2_l[k * 256 + n] : W2_r[(k - 256) * 256 + n];
        g_B2[i] = __float2half_rn(w);
    }
    int totx = n_nodes * 32;
    for (int i = tid; i < totx; i += nthr) {
        int node = i >> 5, q = i & 31;
        float4 v = __ldg((const float4*)(x + (size_t)node * F_IN) + q);
        uint2 p = make_uint2(pack_f16(v.x, v.y), pack_f16(v.z, v.w));
        *((uint2*)(g_xh + (size_t)node * 64) + q) = p;
    }
}

// ---------------- degree histogram ----------------
__global__ void degree_kernel(const void* __restrict__ ei, int E) {
    int e = blockIdx.x * blockDim.x + threadIdx.x;
    if (e < E) {
        int d = edge_at(ei, (size_t)E + e);
        if (d >= 0 && d < N_NODES) atomicAdd(&g_cnt[d], 1);
    }
}

// ---------------- scan ----------------
__global__ void scan1_kernel(int n) {
    __shared__ int sh[1024];
    int i = blockIdx.x * 1024 + threadIdx.x;
    int v = (i < n) ? g_cnt[i] : 0;
    sh[threadIdx.x] = v;
    __syncthreads();
    #pragma unroll
    for (int o = 1; o < 1024; o <<= 1) {
        int add = (threadIdx.x >= o) ? sh[threadIdx.x - o] : 0;
        __syncthreads();
        sh[threadIdx.x] += add;
        __syncthreads();
    }
    if (i < n) g_rowptr[i] = sh[threadIdx.x] - v;
    if (threadIdx.x == 1023) g_bsum[blockIdx.x] = sh[1023];
}

__global__ void scan2_kernel(int nblocks) {
    if (threadIdx.x == 0) {
        int acc = 0;
        for (int b = 0; b < nblocks; b++) {
            int v = g_bsum[b];
            g_bsum[b] = acc;
            acc += v;
        }
    }
}

__global__ void scan3_kernel(int n, int E) {
    int i = blockIdx.x * 1024 + threadIdx.x;
    if (i < n) g_rowptr[i] += g_bsum[blockIdx.x];
    if (i == 0) g_rowptr[n] = E;
}

// ---------------- CSR fill ----------------
__global__ void fill_kernel(const void* __restrict__ ei, int E) {
    int e = blockIdx.x * blockDim.x + threadIdx.x;
    if (e >= E) return;
    int src = edge_at(ei, e);
    int dst = edge_at(ei, (size_t)E + e);
    if ((unsigned)src >= N_NODES || (unsigned)dst >= N_NODES) return;
    int pos = g_rowptr[dst] + atomicAdd(&g_cur[dst], 1);
    g_esrc[pos] = src;
}

// ================= fused gather + fp16 MMA GEMM ==============================
__device__ __forceinline__ void mma16816(float* c, const uint32_t* a, const uint32_t* b) {
    asm volatile(
        "mma.sync.aligned.m16n8k16.row.col.f32.f16.f16.f32 "
        "{%0,%1,%2,%3}, {%4,%5,%6,%7}, {%8,%9}, {%0,%1,%2,%3};"
        : "+f"(c[0]), "+f"(c[1]), "+f"(c[2]), "+f"(c[3])
        : "r"(a[0]), "r"(a[1]), "r"(a[2]), "r"(a[3]), "r"(b[0]), "r"(b[1]));
}

__device__ __forceinline__ void ldsm_x4(uint32_t* r, uint32_t addr) {
    asm volatile("ldmatrix.sync.aligned.m8n8.x4.shared.b16 {%0,%1,%2,%3}, [%4];"
        : "=r"(r[0]), "=r"(r[1]), "=r"(r[2]), "=r"(r[3]) : "r"(addr));
}
__device__ __forceinline__ void ldsm_x2(uint32_t* r, uint32_t addr) {
    asm volatile("ldmatrix.sync.aligned.m8n8.x2.shared.b16 {%0,%1}, [%2];"
        : "=r"(r[0]), "=r"(r[1]) : "r"(addr));
}

__device__ __forceinline__ void cp16(uint32_t smem_byte, const void* gmem) {
    asm volatile("cp.async.cg.shared.global [%0], [%1], 16;" :: "r"(smem_byte), "l"(gmem));
}

// A tile persistent in smem: 128 rows x (KTOT/2) u32, row stride RSA (pad 4 u32)
// B double-buffered: stage = 256 x 20 u32
// LAYER1: RSA = 132, A size = 16896 u32;  LAYER2: RSA = 260, A size = 33280 u32
#define B_STG_U32 5120
#define SMEM_G1 ((16896 + 2 * B_STG_U32) * 4)   // 108,544 B
#define SMEM_G2 ((33280 + 2 * B_STG_U32) * 4)   // 174,080 B

template<int LAYER>
__global__ void __launch_bounds__(256, 1)
fused_gemm_kernel(const float* __restrict__ bias,
                  const float* __restrict__ gamma, const float* __restrict__ beta,
                  const float* __restrict__ mu,    const float* __restrict__ var,
                  float* __restrict__ outp, int n_rows)
{
    constexpr int KTOT = (LAYER == 1) ? 256 : 512;
    constexpr int NCH  = KTOT / 32;
    constexpr int RSA  = (LAYER == 1) ? 132 : 260;   // A row stride (u32)
    constexpr int AU32 = 128 * RSA;
    const __half* B = (LAYER == 1) ? g_B1 : g_B2;

    extern __shared__ uint32_t smu[];
    __shared__ float s_scale[256], s_shift[256];
    __shared__ float s_ss[128];

    const int t = threadIdx.x, wid = t >> 5, lane = t & 31;
    const int grp = lane >> 2, tig = lane & 3;
    const int wm = wid & 3, wn = wid >> 2;
    const int row0 = blockIdx.x * 128;

    uint32_t smem_base;
    asm("{ .reg .u64 tt; cvta.to.shared.u64 tt, %1; cvt.u32.u64 %0, tt; }"
        : "=r"(smem_base) : "l"(smu));

    if (LAYER == 1) {
        float s = gamma[t] * rsqrtf(var[t] + BN_EPS);
        s_scale[t] = s;
        s_shift[t] = beta[t] + (bias[t] - mu[t]) * s;
    } else {
        s_scale[t] = 1.0f;
        s_shift[t] = bias[t];
    }
    if (t < 128) s_ss[t] = 0.0f;

    auto load_B = [&](int ch, int stg) {
        uint32_t sb = smem_base + (AU32 + stg * B_STG_U32) * 4;
        #pragma unroll
        for (int l = 0; l < 4; l++) {
            int id = t + l * 256;
            int n = id >> 2, q = id & 3;
            size_t off = ((size_t)n * KTOT + ch * 32) * 2 + q * 16;
            cp16(sb + (n * 20 + q * 4) * 4, (const char*)B + off);
        }
        asm volatile("cp.async.commit_group;");
    };

    // kick off B chunk 0 prefetch; it overlaps the gather phase below
    load_B(0, 0);

    // ---------------- gather phase: build A tile in smem ----------------
    // warp handles rows wid*16 .. wid*16+15 of the tile
    for (int j = 0; j < 16; j++) {
        int rtile = wid * 16 + j;
        int node = row0 + rtile;
        uint32_t* arow = smu + rtile * RSA;
        if (LAYER == 1) {
            // agg half: mean of x_h neighbor rows (64 u32), lane covers uint2 at lane*2
            float a0 = 0.f, a1 = 0.f, a2 = 0.f, a3 = 0.f;
            uint2 sv = make_uint2(0u, 0u);
            if (node < n_rows) {
                int beg = g_rowptr[node], end = g_rowptr[node + 1];
                float inv = 1.0f / fmaxf((float)(end - beg), 1.0f);
                int i = beg;
                for (; i + 3 < end; i += 4) {
                    int s0 = __ldg(&g_esrc[i]);
                    int s1 = __ldg(&g_esrc[i + 1]);
                    int s2 = __ldg(&g_esrc[i + 2]);
                    int s3 = __ldg(&g_esrc[i + 3]);
                    uint2 v0 = __ldg((const uint2*)(g_xh + (size_t)s0 * 64) + lane);
                    uint2 v1 = __ldg((const uint2*)(g_xh + (size_t)s1 * 64) + lane);
                    uint2 v2 = __ldg((const uint2*)(g_xh + (size_t)s2 * 64) + lane);
                    uint2 v3 = __ldg((const uint2*)(g_xh + (size_t)s3 * 64) + lane);
                    float2 f;
                    f = __half22float2(*(__half2*)&v0.x); a0 += f.x; a1 += f.y;
                    f = __half22float2(*(__half2*)&v0.y); a2 += f.x; a3 += f.y;
                    f = __half22float2(*(__half2*)&v1.x); a0 += f.x; a1 += f.y;
                    f = __half22float2(*(__half2*)&v1.y); a2 += f.x; a3 += f.y;
                    f = __half22float2(*(__half2*)&v2.x); a0 += f.x; a1 += f.y;
                    f = __half22float2(*(__half2*)&v2.y); a2 += f.x; a3 += f.y;
                    f = __half22float2(*(__half2*)&v3.x); a0 += f.x; a1 += f.y;
                    f = __half22float2(*(__half2*)&v3.y); a2 += f.x; a3 += f.y;
                }
                for (; i < end; i++) {
                    int s0 = __ldg(&g_esrc[i]);
                    uint2 v0 = __ldg((const uint2*)(g_xh + (size_t)s0 * 64) + lane);
                    float2 f;
                    f = __half22float2(*(__half2*)&v0.x); a0 += f.x; a1 += f.y;
                    f = __half22float2(*(__half2*)&v0.y); a2 += f.x; a3 += f.y;
                }
                a0 *= inv; a1 *= inv; a2 *= inv; a3 *= inv;
                sv = __ldg((const uint2*)(g_xh + (size_t)node * 64) + lane);
            }
            arow[lane * 2]     = pack_f16(a0, a1);
            arow[lane * 2 + 1] = pack_f16(a2, a3);
            arow[64 + lane * 2]     = sv.x;
            arow[64 + lane * 2 + 1] = sv.y;
        } else {
            // agg half: mean of h1 neighbor rows (128 u32), lane covers uint4 at lane*4
            float acc[8] = {0.f, 0.f, 0.f, 0.f, 0.f, 0.f, 0.f, 0.f};
            uint4 sv = make_uint4(0u, 0u, 0u, 0u);
            if (node < n_rows) {
                int beg = g_rowptr[node], end = g_rowptr[node + 1];
                float inv = 1.0f / fmaxf((float)(end - beg), 1.0f);
                int i = beg;
                for (; i + 3 < end; i += 4) {
                    int s0 = __ldg(&g_esrc[i]);
                    int s1 = __ldg(&g_esrc[i + 1]);
                    int s2 = __ldg(&g_esrc[i + 2]);
                    int s3 = __ldg(&g_esrc[i + 3]);
                    uint4 v0 = __ldg((const uint4*)(g_h1h + (size_t)s0 * 128) + lane);
                    uint4 v1 = __ldg((const uint4*)(g_h1h + (size_t)s1 * 128) + lane);
                    uint4 v2 = __ldg((const uint4*)(g_h1h + (size_t)s2 * 128) + lane);
                    uint4 v3 = __ldg((const uint4*)(g_h1h + (size_t)s3 * 128) + lane);
                    const __half2* h;
                    h = (const __half2*)&v0;
                    #pragma unroll
                    for (int q = 0; q < 4; q++) { float2 f = __half22float2(h[q]); acc[q*2] += f.x; acc[q*2+1] += f.y; }
                    h = (const __half2*)&v1;
                    #pragma unroll
                    for (int q = 0; q < 4; q++) { float2 f = __half22float2(h[q]); acc[q*2] += f.x; acc[q*2+1] += f.y; }
                    h = (const __half2*)&v2;
                    #pragma unroll
                    for (int q = 0; q < 4; q++) { float2 f = __half22float2(h[q]); acc[q*2] += f.x; acc[q*2+1] += f.y; }
                    h = (const __half2*)&v3;
                    #pragma unroll
                    for (int q = 0; q < 4; q++) { float2 f = __half22float2(h[q]); acc[q*2] += f.x; acc[q*2+1] += f.y; }
                }
                for (; i < end; i++) {
                    int s0 = __ldg(&g_esrc[i]);
                    uint4 v0 = __ldg((const uint4*)(g_h1h + (size_t)s0 * 128) + lane);
                    const __half2* h = (const __half2*)&v0;
                    #pragma unroll
                    for (int q = 0; q < 4; q++) { float2 f = __half22float2(h[q]); acc[q*2] += f.x; acc[q*2+1] += f.y; }
                }
                #pragma unroll
                for (int q = 0; q < 8; q++) acc[q] *= inv;
                sv = __ldg((const uint4*)(g_h1h + (size_t)node * 128) + lane);
            }
            uint4 ap;
            ap.x = pack_f16(acc[0], acc[1]);
            ap.y = pack_f16(acc[2], acc[3]);
            ap.z = pack_f16(acc[4], acc[5]);
            ap.w = pack_f16(acc[6], acc[7]);
            *(uint4*)(arow + lane * 4) = ap;
            *(uint4*)(arow + 128 + lane * 4) = sv;
        }
    }
    __syncthreads();

    // ---------------- MMA mainloop ----------------
    float acc[2][16][4];
    #pragma unroll
    for (int mt = 0; mt < 2; mt++)
        #pragma unroll
        for (int nt = 0; nt < 16; nt++)
            #pragma unroll
            for (int q = 0; q < 4; q++) acc[mt][nt][q] = 0.0f;

    const int a_row_in_tile = (lane & 7) + ((lane >> 3) & 1) * 8;
    const int a_kof4 = ((lane >> 4) & 1) * 4;
    const int b_row_in_tile = (lane & 7);
    const int b_kof4 = ((lane >> 3) & 1) * 4;

    for (int ch = 0; ch < NCH; ch++) {
        if (ch + 1 < NCH) {
            load_B(ch + 1, (ch + 1) & 1);
            asm volatile("cp.async.wait_group 1;");
        } else {
            asm volatile("cp.async.wait_group 0;");
        }
        __syncthreads();

        uint32_t sbB = smem_base + (AU32 + (ch & 1) * B_STG_U32) * 4;
        #pragma unroll
        for (int s16 = 0; s16 < 2; s16++) {
            const int pb = s16 * 8;
            uint32_t ah[2][4];
            #pragma unroll
            for (int mt = 0; mt < 2; mt++) {
                int row = wm * 32 + mt * 16 + a_row_in_tile;
                ldsm_x4(ah[mt], smem_base + (row * RSA + ch * 16 + pb + a_kof4) * 4);
            }
            uint32_t baddr0 = sbB + ((wn * 128 + b_row_in_tile) * 20 + pb + b_kof4) * 4;
            #pragma unroll
            for (int nt = 0; nt < 16; nt++) {
                uint32_t bh[2];
                ldsm_x2(bh, baddr0 + nt * 8 * 20 * 4);
                mma16816(acc[0][nt], ah[0], bh);
                mma16816(acc[1][nt], ah[1], bh);
            }
        }
        __syncthreads();
    }

    if (LAYER == 1) {
        // epilogue: BN+ReLU -> h1 (fp16)
        #pragma unroll
        for (int mt = 0; mt < 2; mt++) {
            int r_lo = row0 + wm * 32 + mt * 16 + grp;
            int r_hi = r_lo + 8;
            #pragma unroll
            for (int nt = 0; nt < 16; nt++) {
                int c = wn * 128 + nt * 8 + 2 * tig;
                float s0 = s_scale[c],   sh0 = s_shift[c];
                float s1 = s_scale[c+1], sh1 = s_shift[c+1];
                if (r_lo < n_rows) {
                    float v0 = fmaxf(fmaf(acc[mt][nt][0], s0, sh0), 0.f);
                    float v1 = fmaxf(fmaf(acc[mt][nt][1], s1, sh1), 0.f);
                    g_h1h[(size_t)r_lo * 128 + (c >> 1)] = pack_f16(v0, v1);
                }
                if (r_hi < n_rows) {
                    float v2 = fmaxf(fmaf(acc[mt][nt][2], s0, sh0), 0.f);
                    float v3 = fmaxf(fmaf(acc[mt][nt][3], s1, sh1), 0.f);
                    g_h1h[(size_t)r_hi * 128 + (c >> 1)] = pack_f16(v2, v3);
                }
            }
        }
    } else {
        // epilogue with fused L2 norm
        float ssl[2] = {0.f, 0.f}, ssh[2] = {0.f, 0.f};
        #pragma unroll
        for (int mt = 0; mt < 2; mt++) {
            #pragma unroll
            for (int nt = 0; nt < 16; nt++) {
                int c = wn * 128 + nt * 8 + 2 * tig;
                float v0 = acc[mt][nt][0] + s_shift[c];
                float v1 = acc[mt][nt][1] + s_shift[c + 1];
                float v2 = acc[mt][nt][2] + s_shift[c];
                float v3 = acc[mt][nt][3] + s_shift[c + 1];
                ssl[mt] += v0 * v0 + v1 * v1;
                ssh[mt] += v2 * v2 + v3 * v3;
            }
        }
        #pragma unroll
        for (int mt = 0; mt < 2; mt++) {
            #pragma unroll
            for (int o = 1; o < 4; o <<= 1) {
                ssl[mt] += __shfl_xor_sync(0xFFFFFFFFu, ssl[mt], o);
                ssh[mt] += __shfl_xor_sync(0xFFFFFFFFu, ssh[mt], o);
            }
        }
        if (tig == 0) {
            #pragma unroll
            for (int mt = 0; mt < 2; mt++) {
                atomicAdd(&s_ss[wm * 32 + mt * 16 + grp], ssl[mt]);
                atomicAdd(&s_ss[wm * 32 + mt * 16 + grp + 8], ssh[mt]);
            }
        }
        __syncthreads();
        #pragma unroll
        for (int mt = 0; mt < 2; mt++) {
            int lr = wm * 32 + mt * 16 + grp;
            int r_lo = row0 + lr, r_hi = r_lo + 8;
            float invlo = 1.0f / fmaxf(sqrtf(s_ss[lr]), L2_EPS);
            float invhi = 1.0f / fmaxf(sqrtf(s_ss[lr + 8]), L2_EPS);
            #pragma unroll
            for (int nt = 0; nt < 16; nt++) {
                int c = wn * 128 + nt * 8 + 2 * tig;
                if (r_lo < n_rows) {
                    float v0 = (acc[mt][nt][0] + s_shift[c]) * invlo;
                    float v1 = (acc[mt][nt][1] + s_shift[c + 1]) * invlo;
                    *(float2*)(outp + (size_t)r_lo * 256 + c) = make_float2(v0, v1);
                }
                if (r_hi < n_rows) {
                    float v2 = (acc[mt][nt][2] + s_shift[c]) * invhi;
                    float v3 = (acc[mt][nt][3] + s_shift[c + 1]) * invhi;
                    *(float2*)(outp + (size_t)r_hi * 256 + c) = make_float2(v2, v3);
                }
            }
        }
    }
}

// ---------------- launch ----------------
extern "C" void kernel_launch(void* const* d_in, const int* in_sizes, int n_in,
                              void* d_out, int out_size) {
    const float* x      = (const float*)d_in[0];
    const void*  ei     = d_in[1];
    const float* W1_l   = (const float*)d_in[2];
    const float* b1_l   = (const float*)d_in[3];
    const float* W1_r   = (const float*)d_in[4];
    const float* gamma  = (const float*)d_in[5];
    const float* beta   = (const float*)d_in[6];
    const float* mu     = (const float*)d_in[7];
    const float* var    = (const float*)d_in[8];
    const float* W2_l   = (const float*)d_in[9];
    const float* b2_l   = (const float*)d_in[10];
    const float* W2_r   = (const float*)d_in[11];
    float* out = (float*)d_out;

    const int N = in_sizes[0] / F_IN;     // 100000
    const int E = in_sizes[1] / 2;        // 800000
    const int nsb = (N + 1023) / 1024;

    cudaFuncSetAttribute(fused_gemm_kernel<1>, cudaFuncAttributeMaxDynamicSharedMemorySize, SMEM_G1);
    cudaFuncSetAttribute(fused_gemm_kernel<2>, cudaFuncAttributeMaxDynamicSharedMemorySize, SMEM_G2);

    setup_kernel<<<512, 256>>>((const int*)ei, W1_l, W1_r, W2_l, W2_r, x, N);

    // CSR build
    degree_kernel<<<(E + 255) / 256, 256>>>(ei, E);
    scan1_kernel<<<nsb, 1024>>>(N);
    scan2_kernel<<<1, 32>>>(nsb);
    scan3_kernel<<<nsb, 1024>>>(N, E);
    fill_kernel<<<(E + 255) / 256, 256>>>(ei, E);

    int tiles = (N + 127) / 128;
    // layer 1: fused gather(x) + GEMM + BN + ReLU -> h1 fp16
    fused_gemm_kernel<1><<<tiles, 256, SMEM_G1>>>(b1_l, gamma, beta, mu, var, nullptr, N);
    // layer 2: fused gather(h1) + GEMM + bias + L2 norm -> out
    fused_gemm_kernel<2><<<tiles, 256, SMEM_G2>>>(b2_l, nullptr, nullptr, nullptr, nullptr, out, N);
}

// round 15
// speedup vs baseline: 1.5061x; 1.5061x over previous
#include <cuda_runtime.h>
#include <cuda_fp16.h>
#include <cstdint>

#define N_NODES 100000
#define E_MAX   800000
#define F_IN 128
#define F_H  256
#define BN_EPS 1e-5f
#define L2_EPS 1e-12f

// ---------------- scratch (device globals; referenced ONLY from device code) --
__device__ __align__(16) uint32_t g_h1h[(size_t)N_NODES * 128];  // h1 fp16 packed
__device__ __align__(16) uint32_t g_xh [(size_t)N_NODES * 64];   // x  fp16 packed
__device__ __align__(16) uint32_t g_A1[(size_t)N_NODES * 128];   // [agg128|self128]
__device__ __align__(16) uint32_t g_A2[(size_t)N_NODES * 256];   // [agg256|self256]
__device__ int   g_cnt[N_NODES];
__device__ int   g_cur[N_NODES];
__device__ int   g_rowptr[N_NODES + 1];
__device__ int   g_bsum[128];
__device__ int   g_esrc[E_MAX];
__device__ int   g_is64;

// weights transposed fp16: B[n][k], n = out col (256), k = in
__device__ __align__(16) __half g_B1[256 * 256];
__device__ __align__(16) __half g_B2[256 * 512];

// ---------------- helpers ----------------
__device__ __forceinline__ uint32_t pack_f16(float x, float y) {
    __half2 h = __floats2half2_rn(x, y);
    return *(uint32_t*)&h;
}

__device__ __forceinline__ int edge_at(const void* ei, size_t i) {
    if (g_is64) return (int)((const long long*)ei)[i];
    return ((const int*)ei)[i];
}

// ---------------- setup: detect dtype + zero counters + weight/x fp16 --------
__global__ void setup_kernel(const int* __restrict__ ei_raw,
                             const float* __restrict__ W1_l, const float* __restrict__ W1_r,
                             const float* __restrict__ W2_l, const float* __restrict__ W2_r,
                             const float* __restrict__ x, int n_nodes) {
    if (blockIdx.x == 0) {
        __shared__ int any_nonzero;
        if (threadIdx.x == 0) any_nonzero = 0;
        __syncthreads();
        if (threadIdx.x < 128) {
            int w = ei_raw[threadIdx.x * 2 + 1];
            if (w != 0) atomicOr(&any_nonzero, 1);
        }
        __syncthreads();
        if (threadIdx.x == 0) g_is64 = any_nonzero ? 0 : 1;
    }
    int tid = blockIdx.x * blockDim.x + threadIdx.x;
    int nthr = gridDim.x * blockDim.x;
    for (int i = tid; i < n_nodes; i += nthr) { g_cnt[i] = 0; g_cur[i] = 0; }
    for (int i = tid; i < 256 * 256; i += nthr) {
        int n = i >> 8, k = i & 255;
        float w = (k < 128) ? W1_l[k * 256 + n] : W1_r[(k - 128) * 256 + n];
        g_B1[i] = __float2half_rn(w);
    }
    for (int i = tid; i < 256 * 512; i += nthr) {
        int n = i >> 9, k = i & 511;
        float w = (k < 256) ? W2_l[k * 256 + n] : W2_r[(k - 256) * 256 + n];
        g_B2[i] = __float2half_rn(w);
    }
    int totx = n_nodes * 32;
    for (int i = tid; i < totx; i += nthr) {
        int node = i >> 5, q = i & 31;
        float4 v = __ldg((const float4*)(x + (size_t)node * F_IN) + q);
        uint2 p = make_uint2(pack_f16(v.x, v.y), pack_f16(v.z, v.w));
        *((uint2*)(g_xh + (size_t)node * 64) + q) = p;
    }
}

// ---------------- degree histogram ----------------
__global__ void degree_kernel(const void* __restrict__ ei, int E) {
    int e = blockIdx.x * blockDim.x + threadIdx.x;
    if (e < E) {
        int d = edge_at(ei, (size_t)E + e);
        if (d >= 0 && d < N_NODES) atomicAdd(&g_cnt[d], 1);
    }
}

// ---------------- scan ----------------
__global__ void scan1_kernel(int n) {
    __shared__ int sh[1024];
    int i = blockIdx.x * 1024 + threadIdx.x;
    int v = (i < n) ? g_cnt[i] : 0;
    sh[threadIdx.x] = v;
    __syncthreads();
    #pragma unroll
    for (int o = 1; o < 1024; o <<= 1) {
        int add = (threadIdx.x >= o) ? sh[threadIdx.x - o] : 0;
        __syncthreads();
        sh[threadIdx.x] += add;
        __syncthreads();
    }
    if (i < n) g_rowptr[i] = sh[threadIdx.x] - v;
    if (threadIdx.x == 1023) g_bsum[blockIdx.x] = sh[1023];
}

// parallel exclusive scan of block sums (nblocks <= 128)
__global__ void scan2_kernel(int nblocks) {
    __shared__ int sh[128];
    int i = threadIdx.x;
    int v = (i < nblocks) ? g_bsum[i] : 0;
    sh[i] = v;
    __syncthreads();
    #pragma unroll
    for (int o = 1; o < 128; o <<= 1) {
        int add = (i >= o) ? sh[i - o] : 0;
        __syncthreads();
        sh[i] += add;
        __syncthreads();
    }
    if (i < nblocks) g_bsum[i] = sh[i] - v;
}

__global__ void scan3_kernel(int n, int E) {
    int i = blockIdx.x * 1024 + threadIdx.x;
    if (i < n) g_rowptr[i] += g_bsum[blockIdx.x];
    if (i == 0) g_rowptr[n] = E;
}

// ---------------- CSR fill ----------------
__global__ void fill_kernel(const void* __restrict__ ei, int E) {
    int e = blockIdx.x * blockDim.x + threadIdx.x;
    if (e >= E) return;
    int src = edge_at(ei, e);
    int dst = edge_at(ei, (size_t)E + e);
    if ((unsigned)src >= N_NODES || (unsigned)dst >= N_NODES) return;
    int pos = g_rowptr[dst] + atomicAdd(&g_cur[dst], 1);
    g_esrc[pos] = src;
}

// ---------------- gather layer 1: x fp16 -> A1 agg+self, unroll 4 -----------
__global__ void gather1_kernel(int n_nodes) {
    int node = (blockIdx.x * blockDim.x + threadIdx.x) >> 5;
    int lane = threadIdx.x & 31;
    if (node >= n_nodes) return;
    int beg = g_rowptr[node], end = g_rowptr[node + 1];
    float inv = 1.0f / fmaxf((float)(end - beg), 1.0f);

    float a0 = 0.f, a1 = 0.f, a2 = 0.f, a3 = 0.f;
    int i = beg;
    for (; i + 3 < end; i += 4) {
        int s0 = __ldg(&g_esrc[i]);
        int s1 = __ldg(&g_esrc[i + 1]);
        int s2 = __ldg(&g_esrc[i + 2]);
        int s3 = __ldg(&g_esrc[i + 3]);
        uint2 v0 = __ldg((const uint2*)(g_xh + (size_t)s0 * 64) + lane);
        uint2 v1 = __ldg((const uint2*)(g_xh + (size_t)s1 * 64) + lane);
        uint2 v2 = __ldg((const uint2*)(g_xh + (size_t)s2 * 64) + lane);
        uint2 v3 = __ldg((const uint2*)(g_xh + (size_t)s3 * 64) + lane);
        float2 f;
        f = __half22float2(*(__half2*)&v0.x); a0 += f.x; a1 += f.y;
        f = __half22float2(*(__half2*)&v0.y); a2 += f.x; a3 += f.y;
        f = __half22float2(*(__half2*)&v1.x); a0 += f.x; a1 += f.y;
        f = __half22float2(*(__half2*)&v1.y); a2 += f.x; a3 += f.y;
        f = __half22float2(*(__half2*)&v2.x); a0 += f.x; a1 += f.y;
        f = __half22float2(*(__half2*)&v2.y); a2 += f.x; a3 += f.y;
        f = __half22float2(*(__half2*)&v3.x); a0 += f.x; a1 += f.y;
        f = __half22float2(*(__half2*)&v3.y); a2 += f.x; a3 += f.y;
    }
    for (; i < end; i++) {
        int s0 = __ldg(&g_esrc[i]);
        uint2 v0 = __ldg((const uint2*)(g_xh + (size_t)s0 * 64) + lane);
        float2 f;
        f = __half22float2(*(__half2*)&v0.x); a0 += f.x; a1 += f.y;
        f = __half22float2(*(__half2*)&v0.y); a2 += f.x; a3 += f.y;
    }
    size_t idx = (size_t)node * 128 + lane * 2;
    g_A1[idx]     = pack_f16(a0 * inv, a1 * inv);
    g_A1[idx + 1] = pack_f16(a2 * inv, a3 * inv);
    uint2 sv = __ldg((const uint2*)(g_xh + (size_t)node * 64) + lane);
    *((uint2*)(g_A1 + idx + 64)) = sv;
}

// ---------------- gather layer 2: h1 fp16 -> A2 agg half, unroll 4 ----------
__global__ void gather2_kernel(int n_nodes) {
    int node = (blockIdx.x * blockDim.x + threadIdx.x) >> 5;
    int lane = threadIdx.x & 31;
    if (node >= n_nodes) return;
    int beg = g_rowptr[node], end = g_rowptr[node + 1];
    float inv = 1.0f / fmaxf((float)(end - beg), 1.0f);

    float acc[8] = {0.f, 0.f, 0.f, 0.f, 0.f, 0.f, 0.f, 0.f};
    int i = beg;
    for (; i + 3 < end; i += 4) {
        int s0 = __ldg(&g_esrc[i]);
        int s1 = __ldg(&g_esrc[i + 1]);
        int s2 = __ldg(&g_esrc[i + 2]);
        int s3 = __ldg(&g_esrc[i + 3]);
        uint4 v0 = __ldg((const uint4*)(g_h1h + (size_t)s0 * 128) + lane);
        uint4 v1 = __ldg((const uint4*)(g_h1h + (size_t)s1 * 128) + lane);
        uint4 v2 = __ldg((const uint4*)(g_h1h + (size_t)s2 * 128) + lane);
        uint4 v3 = __ldg((const uint4*)(g_h1h + (size_t)s3 * 128) + lane);
        const __half2* h;
        h = (const __half2*)&v0;
        #pragma unroll
        for (int q = 0; q < 4; q++) { float2 f = __half22float2(h[q]); acc[q*2] += f.x; acc[q*2+1] += f.y; }
        h = (const __half2*)&v1;
        #pragma unroll
        for (int q = 0; q < 4; q++) { float2 f = __half22float2(h[q]); acc[q*2] += f.x; acc[q*2+1] += f.y; }
        h = (const __half2*)&v2;
        #pragma unroll
        for (int q = 0; q < 4; q++) { float2 f = __half22float2(h[q]); acc[q*2] += f.x; acc[q*2+1] += f.y; }
        h = (const __half2*)&v3;
        #pragma unroll
        for (int q = 0; q < 4; q++) { float2 f = __half22float2(h[q]); acc[q*2] += f.x; acc[q*2+1] += f.y; }
    }
    for (; i < end; i++) {
        int s0 = __ldg(&g_esrc[i]);
        uint4 v0 = __ldg((const uint4*)(g_h1h + (size_t)s0 * 128) + lane);
        const __half2* h = (const __half2*)&v0;
        #pragma unroll
        for (int q = 0; q < 4; q++) { float2 f = __half22float2(h[q]); acc[q*2] += f.x; acc[q*2+1] += f.y; }
    }
    uint32_t outw[4];
    #pragma unroll
    for (int q = 0; q < 4; q++)
        outw[q] = pack_f16(acc[q * 2] * inv, acc[q * 2 + 1] * inv);
    *((uint4*)(g_A2 + (size_t)node * 256) + lane) = *(uint4*)outw;
}

// ================= warp-level fp16 MMA GEMM, cp.async + ldmatrix =============
__device__ __forceinline__ void mma16816(float* c, const uint32_t* a, const uint32_t* b) {
    asm volatile(
        "mma.sync.aligned.m16n8k16.row.col.f32.f16.f16.f32 "
        "{%0,%1,%2,%3}, {%4,%5,%6,%7}, {%8,%9}, {%0,%1,%2,%3};"
        : "+f"(c[0]), "+f"(c[1]), "+f"(c[2]), "+f"(c[3])
        : "r"(a[0]), "r"(a[1]), "r"(a[2]), "r"(a[3]), "r"(b[0]), "r"(b[1]));
}

__device__ __forceinline__ void ldsm_x4(uint32_t* r, uint32_t addr) {
    asm volatile("ldmatrix.sync.aligned.m8n8.x4.shared.b16 {%0,%1,%2,%3}, [%4];"
        : "=r"(r[0]), "=r"(r[1]), "=r"(r[2]), "=r"(r[3]) : "r"(addr));
}
__device__ __forceinline__ void ldsm_x2(uint32_t* r, uint32_t addr) {
    asm volatile("ldmatrix.sync.aligned.m8n8.x2.shared.b16 {%0,%1}, [%2];"
        : "=r"(r[0]), "=r"(r[1]) : "r"(addr));
}

__device__ __forceinline__ void cp16(uint32_t smem_byte, const void* gmem) {
    asm volatile("cp.async.cg.shared.global [%0], [%1], 16;" :: "r"(smem_byte), "l"(gmem));
}

// stage layout (u32): A@0 (128x20), B@2560 (256x20)
#define SM_A 0
#define SM_B 2560
#define STG_U32 7680
#define SMEM_MMA (2 * STG_U32 * 4)     // 61440 B

template<int LAYER>
__global__ void __launch_bounds__(256, 1)
mma_gemm_kernel(const float* __restrict__ bias,
                const float* __restrict__ gamma, const float* __restrict__ beta,
                const float* __restrict__ mu,    const float* __restrict__ var,
                float* __restrict__ outp, int n_rows)
{
    constexpr int KTOT = (LAYER == 1) ? 256 : 512;
    constexpr int NCH  = KTOT / 32;
    constexpr int RS   = KTOT / 2;        // A row stride in u32
    const uint32_t* A = (LAYER == 1) ? g_A1 : g_A2;
    const __half* B   = (LAYER == 1) ? g_B1 : g_B2;

    extern __shared__ uint32_t smu[];
    __shared__ float s_scale[256], s_shift[256];
    __shared__ float s_ss[128];

    const int t = threadIdx.x, wid = t >> 5, lane = t & 31;
    const int grp = lane >> 2, tig = lane & 3;
    const int wm = wid & 3, wn = wid >> 2;
    const int row0 = blockIdx.x * 128;

    uint32_t smem_base;
    asm("{ .reg .u64 tt; cvta.to.shared.u64 tt, %1; cvt.u32.u64 %0, tt; }"
        : "=r"(smem_base) : "l"(smu));

    if (LAYER == 1) {
        float s = gamma[t] * rsqrtf(var[t] + BN_EPS);
        s_scale[t] = s;
        s_shift[t] = beta[t] + (bias[t] - mu[t]) * s;
    } else {
        s_scale[t] = 1.0f;
        s_shift[t] = bias[t];
    }
    if (t < 128) s_ss[t] = 0.0f;

    auto load_chunk = [&](int ch, int stg) {
        uint32_t sb = smem_base + stg * (STG_U32 * 4);
        #pragma unroll
        for (int l = 0; l < 2; l++) {
            int id = t + l * 256;
            int r = id >> 2, q = id & 3;
            int gr = row0 + r;
            if (gr >= n_rows) gr = n_rows - 1;
            size_t off = ((size_t)gr * RS + ch * 16 + q * 4) * 4;
            cp16(sb + (SM_A + r * 20 + q * 4) * 4, (const char*)A + off);
        }
        #pragma unroll
        for (int l = 0; l < 4; l++) {
            int id = t + l * 256;
            int n = id >> 2, q = id & 3;
            size_t off = ((size_t)n * KTOT + ch * 32) * 2 + q * 16;
            cp16(sb + (SM_B + n * 20 + q * 4) * 4, (const char*)B + off);
        }
        asm volatile("cp.async.commit_group;");
    };

    float acc[2][16][4];
    #pragma unroll
    for (int mt = 0; mt < 2; mt++)
        #pragma unroll
        for (int nt = 0; nt < 16; nt++)
            #pragma unroll
            for (int q = 0; q < 4; q++) acc[mt][nt][q] = 0.0f;

    const int a_row_in_tile = (lane & 7) + ((lane >> 3) & 1) * 8;
    const int a_kof4 = ((lane >> 4) & 1) * 4;
    const int b_row_in_tile = (lane & 7);
    const int b_kof4 = ((lane >> 3) & 1) * 4;

    load_chunk(0, 0);

    for (int ch = 0; ch < NCH; ch++) {
        if (ch + 1 < NCH) {
            load_chunk(ch + 1, (ch + 1) & 1);
            asm volatile("cp.async.wait_group 1;");
        } else {
            asm volatile("cp.async.wait_group 0;");
        }
        __syncthreads();

        uint32_t sb = smem_base + (ch & 1) * (STG_U32 * 4);
        #pragma unroll
        for (int s16 = 0; s16 < 2; s16++) {
            const int pb = s16 * 8;
            uint32_t ah[2][4];
            #pragma unroll
            for (int mt = 0; mt < 2; mt++) {
                int row = wm * 32 + mt * 16 + a_row_in_tile;
                ldsm_x4(ah[mt], sb + (SM_A + row * 20 + pb + a_kof4) * 4);
            }
            uint32_t baddr0 = sb + (SM_B + (wn * 128 + b_row_in_tile) * 20 + pb + b_kof4) * 4;
            #pragma unroll
            for (int nt = 0; nt < 16; nt++) {
                uint32_t bh[2];
                ldsm_x2(bh, baddr0 + nt * 8 * 20 * 4);
                mma16816(acc[0][nt], ah[0], bh);
                mma16816(acc[1][nt], ah[1], bh);
            }
        }
        __syncthreads();
    }

    if (LAYER == 1) {
        #pragma unroll
        for (int mt = 0; mt < 2; mt++) {
            int r_lo = row0 + wm * 32 + mt * 16 + grp;
            int r_hi = r_lo + 8;
            #pragma unroll
            for (int nt = 0; nt < 16; nt++) {
                int c = wn * 128 + nt * 8 + 2 * tig;
                float s0 = s_scale[c],   sh0 = s_shift[c];
                float s1 = s_scale[c+1], sh1 = s_shift[c+1];
                if (r_lo < n_rows) {
                    float v0 = fmaxf(fmaf(acc[mt][nt][0], s0, sh0), 0.f);
                    float v1 = fmaxf(fmaf(acc[mt][nt][1], s1, sh1), 0.f);
                    uint32_t pw = pack_f16(v0, v1);
                    g_h1h[(size_t)r_lo * 128 + (c >> 1)] = pw;
                    g_A2[(size_t)r_lo * 256 + 128 + (c >> 1)] = pw;
                }
                if (r_hi < n_rows) {
                    float v2 = fmaxf(fmaf(acc[mt][nt][2], s0, sh0), 0.f);
                    float v3 = fmaxf(fmaf(acc[mt][nt][3], s1, sh1), 0.f);
                    uint32_t pw = pack_f16(v2, v3);
                    g_h1h[(size_t)r_hi * 128 + (c >> 1)] = pw;
                    g_A2[(size_t)r_hi * 256 + 128 + (c >> 1)] = pw;
                }
            }
        }
    } else {
        float ssl[2] = {0.f, 0.f}, ssh[2] = {0.f, 0.f};
        #pragma unroll
        for (int mt = 0; mt < 2; mt++) {
            #pragma unroll
            for (int nt = 0; nt < 16; nt++) {
                int c = wn * 128 + nt * 8 + 2 * tig;
                float v0 = acc[mt][nt][0] + s_shift[c];
                float v1 = acc[mt][nt][1] + s_shift[c + 1];
                float v2 = acc[mt][nt][2] + s_shift[c];
                float v3 = acc[mt][nt][3] + s_shift[c + 1];
                ssl[mt] += v0 * v0 + v1 * v1;
                ssh[mt] += v2 * v2 + v3 * v3;
            }
        }
        #pragma unroll
        for (int mt = 0; mt < 2; mt++) {
            #pragma unroll
            for (int o = 1; o < 4; o <<= 1) {
                ssl[mt] += __shfl_xor_sync(0xFFFFFFFFu, ssl[mt], o);
                ssh[mt] += __shfl_xor_sync(0xFFFFFFFFu, ssh[mt], o);
            }
        }
        if (tig == 0) {
            #pragma unroll
            for (int mt = 0; mt < 2; mt++) {
                atomicAdd(&s_ss[wm * 32 + mt * 16 + grp], ssl[mt]);
                atomicAdd(&s_ss[wm * 32 + mt * 16 + grp + 8], ssh[mt]);
            }
        }
        __syncthreads();
        #pragma unroll
        for (int mt = 0; mt < 2; mt++) {
            int lr = wm * 32 + mt * 16 + grp;
            int r_lo = row0 + lr, r_hi = r_lo + 8;
            float invlo = 1.0f / fmaxf(sqrtf(s_ss[lr]), L2_EPS);
            float invhi = 1.0f / fmaxf(sqrtf(s_ss[lr + 8]), L2_EPS);
            #pragma unroll
            for (int nt = 0; nt < 16; nt++) {
                int c = wn * 128 + nt * 8 + 2 * tig;
                if (r_lo < n_rows) {
                    float v0 = (acc[mt][nt][0] + s_shift[c]) * invlo;
                    float v1 = (acc[mt][nt][1] + s_shift[c + 1]) * invlo;
                    *(float2*)(outp + (size_t)r_lo * 256 + c) = make_float2(v0, v1);
                }
                if (r_hi < n_rows) {
                    float v2 = (acc[mt][nt][2] + s_shift[c]) * invhi;
                    float v3 = (acc[mt][nt][3] + s_shift[c + 1]) * invhi;
                    *(float2*)(outp + (size_t)r_hi * 256 + c) = make_float2(v2, v3);
                }
            }
        }
    }
}

// ---------------- launch ----------------
extern "C" void kernel_launch(void* const* d_in, const int* in_sizes, int n_in,
                              void* d_out, int out_size) {
    const float* x      = (const float*)d_in[0];
    const void*  ei     = d_in[1];
    const float* W1_l   = (const float*)d_in[2];
    const float* b1_l   = (const float*)d_in[3];
    const float* W1_r   = (const float*)d_in[4];
    const float* gamma  = (const float*)d_in[5];
    const float* beta   = (const float*)d_in[6];
    const float* mu     = (const float*)d_in[7];
    const float* var    = (const float*)d_in[8];
    const float* W2_l   = (const float*)d_in[9];
    const float* b2_l   = (const float*)d_in[10];
    const float* W2_r   = (const float*)d_in[11];
    float* out = (float*)d_out;

    const int N = in_sizes[0] / F_IN;     // 100000
    const int E = in_sizes[1] / 2;        // 800000
    const int nsb = (N + 1023) / 1024;

    cudaFuncSetAttribute(mma_gemm_kernel<1>, cudaFuncAttributeMaxDynamicSharedMemorySize, SMEM_MMA);
    cudaFuncSetAttribute(mma_gemm_kernel<2>, cudaFuncAttributeMaxDynamicSharedMemorySize, SMEM_MMA);

    setup_kernel<<<512, 256>>>((const int*)ei, W1_l, W1_r, W2_l, W2_r, x, N);

    // CSR build
    degree_kernel<<<(E + 255) / 256, 256>>>(ei, E);
    scan1_kernel<<<nsb, 1024>>>(N);
    scan2_kernel<<<1, 128>>>(nsb);
    scan3_kernel<<<nsb, 1024>>>(N, E);
    fill_kernel<<<(E + 255) / 256, 256>>>(ei, E);

    // layer-1: A1 = [mean(x nbrs) | x]  (fp16)
    gather1_kernel<<<(N * 32 + 255) / 256, 256>>>(N);

    // h1 = relu(BN(A1 @ B1)) -> g_h1h fp16 (+ A2 self half)
    {
        int tiles = (N + 127) / 128;
        mma_gemm_kernel<1><<<tiles, 256, SMEM_MMA>>>(b1_l, gamma, beta, mu, var, nullptr, N);
    }

    // layer-2: A2[:, 0:256] = mean(h1 nbrs)
    gather2_kernel<<<(N * 32 + 255) / 256, 256>>>(N);

    // out = l2norm(A2 @ B2 + b2)
    {
        int tiles = (N + 127) / 128;
        mma_gemm_kernel<2><<<tiles, 256, SMEM_MMA>>>(b2_l, nullptr, nullptr, nullptr, nullptr, out, N);
    }
}

// round 16
// speedup vs baseline: 1.6876x; 1.1205x over previous
#include <cuda_runtime.h>
#include <cuda_fp16.h>
#include <cstdint>

#define N_NODES 100000
#define E_MAX   800000
#define F_IN 128
#define F_H  256
#define BN_EPS 1e-5f
#define L2_EPS 1e-12f

// ---------------- scratch (device globals; referenced ONLY from device code) --
__device__ __align__(16) uint32_t g_h1h[(size_t)N_NODES * 128];  // h1 fp16 packed
__device__ __align__(16) uint32_t g_xh [(size_t)N_NODES * 64];   // x  fp16 packed
__device__ __align__(16) uint32_t g_A1[(size_t)N_NODES * 128];   // [agg128|self128]
__device__ __align__(16) uint32_t g_A2[(size_t)N_NODES * 128];   // agg256 only
__device__ int   g_cnt[N_NODES];
__device__ int   g_cur[N_NODES];
__device__ int   g_rowptr[N_NODES + 1];
__device__ int   g_bsum[128];
__device__ int   g_esrc[E_MAX];
__device__ int   g_is64;

// weights transposed fp16: B[n][k], n = out col (256), k = in
__device__ __align__(16) __half g_B1[256 * 256];
__device__ __align__(16) __half g_B2[256 * 512];

// ---------------- helpers ----------------
__device__ __forceinline__ uint32_t pack_f16(float x, float y) {
    __half2 h = __floats2half2_rn(x, y);
    return *(uint32_t*)&h;
}

__device__ __forceinline__ int edge_at(const void* ei, size_t i) {
    if (g_is64) return (int)((const long long*)ei)[i];
    return ((const int*)ei)[i];
}

// ---------------- detect dtype ----------------
__global__ void detect_kernel(const int* __restrict__ ei_raw) {
    __shared__ int any_nonzero;
    if (threadIdx.x == 0) any_nonzero = 0;
    __syncthreads();
    int w = ei_raw[threadIdx.x * 2 + 1];
    if (w != 0) atomicOr(&any_nonzero, 1);
    __syncthreads();
    if (threadIdx.x == 0) g_is64 = any_nonzero ? 0 : 1;
}

// ---------------- zero counters (CSR stream) ----------------
__global__ void zero_kernel() {
    int i = blockIdx.x * blockDim.x + threadIdx.x;
    if (i < N_NODES) { g_cnt[i] = 0; g_cur[i] = 0; }
}

// ---------------- setup: weight fp16 transpose + x fp16 (main stream) --------
__global__ void setup_kernel(const float* __restrict__ W1_l, const float* __restrict__ W1_r,
                             const float* __restrict__ W2_l, const float* __restrict__ W2_r,
                             const float* __restrict__ x, int n_nodes) {
    int tid = blockIdx.x * blockDim.x + threadIdx.x;
    int nthr = gridDim.x * blockDim.x;
    for (int i = tid; i < 256 * 256; i += nthr) {
        int n = i >> 8, k = i & 255;
        float w = (k < 128) ? W1_l[k * 256 + n] : W1_r[(k - 128) * 256 + n];
        g_B1[i] = __float2half_rn(w);
    }
    for (int i = tid; i < 256 * 512; i += nthr) {
        int n = i >> 9, k = i & 511;
        float w = (k < 256) ? W2_l[k * 256 + n] : W2_r[(k - 256) * 256 + n];
        g_B2[i] = __float2half_rn(w);
    }
    int totx = n_nodes * 32;
    for (int i = tid; i < totx; i += nthr) {
        int node = i >> 5, q = i & 31;
        float4 v = __ldg((const float4*)(x + (size_t)node * F_IN) + q);
        uint2 p = make_uint2(pack_f16(v.x, v.y), pack_f16(v.z, v.w));
        *((uint2*)(g_xh + (size_t)node * 64) + q) = p;
    }
}

// ---------------- degree histogram ----------------
__global__ void degree_kernel(const void* __restrict__ ei, int E) {
    int e = blockIdx.x * blockDim.x + threadIdx.x;
    if (e < E) {
        int d = edge_at(ei, (size_t)E + e);
        if (d >= 0 && d < N_NODES) atomicAdd(&g_cnt[d], 1);
    }
}

// ---------------- scan ----------------
__global__ void scan1_kernel(int n) {
    __shared__ int sh[1024];
    int i = blockIdx.x * 1024 + threadIdx.x;
    int v = (i < n) ? g_cnt[i] : 0;
    sh[threadIdx.x] = v;
    __syncthreads();
    #pragma unroll
    for (int o = 1; o < 1024; o <<= 1) {
        int add = (threadIdx.x >= o) ? sh[threadIdx.x - o] : 0;
        __syncthreads();
        sh[threadIdx.x] += add;
        __syncthreads();
    }
    if (i < n) g_rowptr[i] = sh[threadIdx.x] - v;
    if (threadIdx.x == 1023) g_bsum[blockIdx.x] = sh[1023];
}

__global__ void scan2_kernel(int nblocks) {
    __shared__ int sh[128];
    int i = threadIdx.x;
    int v = (i < nblocks) ? g_bsum[i] : 0;
    sh[i] = v;
    __syncthreads();
    #pragma unroll
    for (int o = 1; o < 128; o <<= 1) {
        int add = (i >= o) ? sh[i - o] : 0;
        __syncthreads();
        sh[i] += add;
        __syncthreads();
    }
    if (i < nblocks) g_bsum[i] = sh[i] - v;
}

__global__ void scan3_kernel(int n, int E) {
    int i = blockIdx.x * 1024 + threadIdx.x;
    if (i < n) g_rowptr[i] += g_bsum[blockIdx.x];
    if (i == 0) g_rowptr[n] = E;
}

// ---------------- CSR fill ----------------
__global__ void fill_kernel(const void* __restrict__ ei, int E) {
    int e = blockIdx.x * blockDim.x + threadIdx.x;
    if (e >= E) return;
    int src = edge_at(ei, e);
    int dst = edge_at(ei, (size_t)E + e);
    if ((unsigned)src >= N_NODES || (unsigned)dst >= N_NODES) return;
    int pos = g_rowptr[dst] + atomicAdd(&g_cur[dst], 1);
    g_esrc[pos] = src;
}

// ---------------- gather layer 1: x fp16 -> A1 agg+self, unroll 4 -----------
__global__ void gather1_kernel(int n_nodes) {
    int node = (blockIdx.x * blockDim.x + threadIdx.x) >> 5;
    int lane = threadIdx.x & 31;
    if (node >= n_nodes) return;
    int beg = g_rowptr[node], end = g_rowptr[node + 1];
    float inv = 1.0f / fmaxf((float)(end - beg), 1.0f);

    float a0 = 0.f, a1 = 0.f, a2 = 0.f, a3 = 0.f;
    int i = beg;
    for (; i + 3 < end; i += 4) {
        int s0 = __ldg(&g_esrc[i]);
        int s1 = __ldg(&g_esrc[i + 1]);
        int s2 = __ldg(&g_esrc[i + 2]);
        int s3 = __ldg(&g_esrc[i + 3]);
        uint2 v0 = __ldg((const uint2*)(g_xh + (size_t)s0 * 64) + lane);
        uint2 v1 = __ldg((const uint2*)(g_xh + (size_t)s1 * 64) + lane);
        uint2 v2 = __ldg((const uint2*)(g_xh + (size_t)s2 * 64) + lane);
        uint2 v3 = __ldg((const uint2*)(g_xh + (size_t)s3 * 64) + lane);
        float2 f;
        f = __half22float2(*(__half2*)&v0.x); a0 += f.x; a1 += f.y;
        f = __half22float2(*(__half2*)&v0.y); a2 += f.x; a3 += f.y;
        f = __half22float2(*(__half2*)&v1.x); a0 += f.x; a1 += f.y;
        f = __half22float2(*(__half2*)&v1.y); a2 += f.x; a3 += f.y;
        f = __half22float2(*(__half2*)&v2.x); a0 += f.x; a1 += f.y;
        f = __half22float2(*(__half2*)&v2.y); a2 += f.x; a3 += f.y;
        f = __half22float2(*(__half2*)&v3.x); a0 += f.x; a1 += f.y;
        f = __half22float2(*(__half2*)&v3.y); a2 += f.x; a3 += f.y;
    }
    for (; i < end; i++) {
        int s0 = __ldg(&g_esrc[i]);
        uint2 v0 = __ldg((const uint2*)(g_xh + (size_t)s0 * 64) + lane);
        float2 f;
        f = __half22float2(*(__half2*)&v0.x); a0 += f.x; a1 += f.y;
        f = __half22float2(*(__half2*)&v0.y); a2 += f.x; a3 += f.y;
    }
    size_t idx = (size_t)node * 128 + lane * 2;
    g_A1[idx]     = pack_f16(a0 * inv, a1 * inv);
    g_A1[idx + 1] = pack_f16(a2 * inv, a3 * inv);
    uint2 sv = __ldg((const uint2*)(g_xh + (size_t)node * 64) + lane);
    *((uint2*)(g_A1 + idx + 64)) = sv;
}

// ---------------- gather layer 2: h1 fp16 -> A2 (agg only), unroll 4 --------
__global__ void gather2_kernel(int n_nodes) {
    int node = (blockIdx.x * blockDim.x + threadIdx.x) >> 5;
    int lane = threadIdx.x & 31;
    if (node >= n_nodes) return;
    int beg = g_rowptr[node], end = g_rowptr[node + 1];
    float inv = 1.0f / fmaxf((float)(end - beg), 1.0f);

    float acc[8] = {0.f, 0.f, 0.f, 0.f, 0.f, 0.f, 0.f, 0.f};
    int i = beg;
    for (; i + 3 < end; i += 4) {
        int s0 = __ldg(&g_esrc[i]);
        int s1 = __ldg(&g_esrc[i + 1]);
        int s2 = __ldg(&g_esrc[i + 2]);
        int s3 = __ldg(&g_esrc[i + 3]);
        uint4 v0 = __ldg((const uint4*)(g_h1h + (size_t)s0 * 128) + lane);
        uint4 v1 = __ldg((const uint4*)(g_h1h + (size_t)s1 * 128) + lane);
        uint4 v2 = __ldg((const uint4*)(g_h1h + (size_t)s2 * 128) + lane);
        uint4 v3 = __ldg((const uint4*)(g_h1h + (size_t)s3 * 128) + lane);
        const __half2* h;
        h = (const __half2*)&v0;
        #pragma unroll
        for (int q = 0; q < 4; q++) { float2 f = __half22float2(h[q]); acc[q*2] += f.x; acc[q*2+1] += f.y; }
        h = (const __half2*)&v1;
        #pragma unroll
        for (int q = 0; q < 4; q++) { float2 f = __half22float2(h[q]); acc[q*2] += f.x; acc[q*2+1] += f.y; }
        h = (const __half2*)&v2;
        #pragma unroll
        for (int q = 0; q < 4; q++) { float2 f = __half22float2(h[q]); acc[q*2] += f.x; acc[q*2+1] += f.y; }
        h = (const __half2*)&v3;
        #pragma unroll
        for (int q = 0; q < 4; q++) { float2 f = __half22float2(h[q]); acc[q*2] += f.x; acc[q*2+1] += f.y; }
    }
    for (; i < end; i++) {
        int s0 = __ldg(&g_esrc[i]);
        uint4 v0 = __ldg((const uint4*)(g_h1h + (size_t)s0 * 128) + lane);
        const __half2* h = (const __half2*)&v0;
        #pragma unroll
        for (int q = 0; q < 4; q++) { float2 f = __half22float2(h[q]); acc[q*2] += f.x; acc[q*2+1] += f.y; }
    }
    uint32_t outw[4];
    #pragma unroll
    for (int q = 0; q < 4; q++)
        outw[q] = pack_f16(acc[q * 2] * inv, acc[q * 2 + 1] * inv);
    *((uint4*)(g_A2 + (size_t)node * 128) + lane) = *(uint4*)outw;
}

// ================= warp-level fp16 MMA GEMM, cp.async + ldmatrix =============
__device__ __forceinline__ void mma16816(float* c, const uint32_t* a, const uint32_t* b) {
    asm volatile(
        "mma.sync.aligned.m16n8k16.row.col.f32.f16.f16.f32 "
        "{%0,%1,%2,%3}, {%4,%5,%6,%7}, {%8,%9}, {%0,%1,%2,%3};"
        : "+f"(c[0]), "+f"(c[1]), "+f"(c[2]), "+f"(c[3])
        : "r"(a[0]), "r"(a[1]), "r"(a[2]), "r"(a[3]), "r"(b[0]), "r"(b[1]));
}

__device__ __forceinline__ void ldsm_x4(uint32_t* r, uint32_t addr) {
    asm volatile("ldmatrix.sync.aligned.m8n8.x4.shared.b16 {%0,%1,%2,%3}, [%4];"
        : "=r"(r[0]), "=r"(r[1]), "=r"(r[2]), "=r"(r[3]) : "r"(addr));
}
__device__ __forceinline__ void ldsm_x2(uint32_t* r, uint32_t addr) {
    asm volatile("ldmatrix.sync.aligned.m8n8.x2.shared.b16 {%0,%1}, [%2];"
        : "=r"(r[0]), "=r"(r[1]) : "r"(addr));
}

__device__ __forceinline__ void cp16(uint32_t smem_byte, const void* gmem) {
    asm volatile("cp.async.cg.shared.global [%0], [%1], 16;" :: "r"(smem_byte), "l"(gmem));
}

// stage layout (u32): A@0 (128x20), B@2560 (256x20)
#define SM_A 0
#define SM_B 2560
#define STG_U32 7680
#define SMEM_MMA (2 * STG_U32 * 4)     // 61440 B

template<int LAYER>
__global__ void __launch_bounds__(256, 1)
mma_gemm_kernel(const float* __restrict__ bias,
                const float* __restrict__ gamma, const float* __restrict__ beta,
                const float* __restrict__ mu,    const float* __restrict__ var,
                float* __restrict__ outp, int n_rows)
{
    constexpr int KTOT = (LAYER == 1) ? 256 : 512;
    constexpr int NCH  = KTOT / 32;
    const __half* B = (LAYER == 1) ? g_B1 : g_B2;

    extern __shared__ uint32_t smu[];
    __shared__ float s_scale[256], s_shift[256];
    __shared__ float s_ss[128];

    const int t = threadIdx.x, wid = t >> 5, lane = t & 31;
    const int grp = lane >> 2, tig = lane & 3;
    const int wm = wid & 3, wn = wid >> 2;
    const int row0 = blockIdx.x * 128;

    uint32_t smem_base;
    asm("{ .reg .u64 tt; cvta.to.shared.u64 tt, %1; cvt.u32.u64 %0, tt; }"
        : "=r"(smem_base) : "l"(smu));

    if (LAYER == 1) {
        float s = gamma[t] * rsqrtf(var[t] + BN_EPS);
        s_scale[t] = s;
        s_shift[t] = beta[t] + (bias[t] - mu[t]) * s;
    } else {
        s_scale[t] = 1.0f;
        s_shift[t] = bias[t];
    }
    if (t < 128) s_ss[t] = 0.0f;

    // A sources: LAYER1 = g_A1 [N][128]; LAYER2 = agg g_A2 [N][128] (ch 0..7),
    // self g_h1h [N][128] (ch 8..15). All row stride 128 u32.
    auto load_chunk = [&](int ch, int stg) {
        uint32_t sb = smem_base + stg * (STG_U32 * 4);
        const uint32_t* Abase;
        int coff;
        if (LAYER == 1)      { Abase = g_A1;  coff = ch * 16; }
        else if (ch < 8)     { Abase = g_A2;  coff = ch * 16; }
        else                 { Abase = g_h1h; coff = (ch - 8) * 16; }
        #pragma unroll
        for (int l = 0; l < 2; l++) {
            int id = t + l * 256;
            int r = id >> 2, q = id & 3;
            int gr = row0 + r;
            if (gr >= n_rows) gr = n_rows - 1;
            size_t off = ((size_t)gr * 128 + coff + q * 4) * 4;
            cp16(sb + (SM_A + r * 20 + q * 4) * 4, (const char*)Abase + off);
        }
        #pragma unroll
        for (int l = 0; l < 4; l++) {
            int id = t + l * 256;
            int n = id >> 2, q = id & 3;
            size_t off = ((size_t)n * KTOT + ch * 32) * 2 + q * 16;
            cp16(sb + (SM_B + n * 20 + q * 4) * 4, (const char*)B + off);
        }
        asm volatile("cp.async.commit_group;");
    };

    float acc[2][16][4];
    #pragma unroll
    for (int mt = 0; mt < 2; mt++)
        #pragma unroll
        for (int nt = 0; nt < 16; nt++)
            #pragma unroll
            for (int q = 0; q < 4; q++) acc[mt][nt][q] = 0.0f;

    const int a_row_in_tile = (lane & 7) + ((lane >> 3) & 1) * 8;
    const int a_kof4 = ((lane >> 4) & 1) * 4;
    const int b_row_in_tile = (lane & 7);
    const int b_kof4 = ((lane >> 3) & 1) * 4;

    load_chunk(0, 0);

    for (int ch = 0; ch < NCH; ch++) {
        if (ch + 1 < NCH) {
            load_chunk(ch + 1, (ch + 1) & 1);
            asm volatile("cp.async.wait_group 1;");
        } else {
            asm volatile("cp.async.wait_group 0;");
        }
        __syncthreads();

        uint32_t sb = smem_base + (ch & 1) * (STG_U32 * 4);
        #pragma unroll
        for (int s16 = 0; s16 < 2; s16++) {
            const int pb = s16 * 8;
            uint32_t ah[2][4];
            #pragma unroll
            for (int mt = 0; mt < 2; mt++) {
                int row = wm * 32 + mt * 16 + a_row_in_tile;
                ldsm_x4(ah[mt], sb + (SM_A + row * 20 + pb + a_kof4) * 4);
            }
            uint32_t baddr0 = sb + (SM_B + (wn * 128 + b_row_in_tile) * 20 + pb + b_kof4) * 4;
            #pragma unroll
            for (int nt = 0; nt < 16; nt++) {
                uint32_t bh[2];
                ldsm_x2(bh, baddr0 + nt * 8 * 20 * 4);
                mma16816(acc[0][nt], ah[0], bh);
                mma16816(acc[1][nt], ah[1], bh);
            }
        }
        __syncthreads();
    }

    if (LAYER == 1) {
        #pragma unroll
        for (int mt = 0; mt < 2; mt++) {
            int r_lo = row0 + wm * 32 + mt * 16 + grp;
            int r_hi = r_lo + 8;
            #pragma unroll
            for (int nt = 0; nt < 16; nt++) {
                int c = wn * 128 + nt * 8 + 2 * tig;
                float s0 = s_scale[c],   sh0 = s_shift[c];
                float s1 = s_scale[c+1], sh1 = s_shift[c+1];
                if (r_lo < n_rows) {
                    float v0 = fmaxf(fmaf(acc[mt][nt][0], s0, sh0), 0.f);
                    float v1 = fmaxf(fmaf(acc[mt][nt][1], s1, sh1), 0.f);
                    g_h1h[(size_t)r_lo * 128 + (c >> 1)] = pack_f16(v0, v1);
                }
                if (r_hi < n_rows) {
                    float v2 = fmaxf(fmaf(acc[mt][nt][2], s0, sh0), 0.f);
                    float v3 = fmaxf(fmaf(acc[mt][nt][3], s1, sh1), 0.f);
                    g_h1h[(size_t)r_hi * 128 + (c >> 1)] = pack_f16(v2, v3);
                }
            }
        }
    } else {
        float ssl[2] = {0.f, 0.f}, ssh[2] = {0.f, 0.f};
        #pragma unroll
        for (int mt = 0; mt < 2; mt++) {
            #pragma unroll
            for (int nt = 0; nt < 16; nt++) {
                int c = wn * 128 + nt * 8 + 2 * tig;
                float v0 = acc[mt][nt][0] + s_shift[c];
                float v1 = acc[mt][nt][1] + s_shift[c + 1];
                float v2 = acc[mt][nt][2] + s_shift[c];
                float v3 = acc[mt][nt][3] + s_shift[c + 1];
                ssl[mt] += v0 * v0 + v1 * v1;
                ssh[mt] += v2 * v2 + v3 * v3;
            }
        }
        #pragma unroll
        for (int mt = 0; mt < 2; mt++) {
            #pragma unroll
            for (int o = 1; o < 4; o <<= 1) {
                ssl[mt] += __shfl_xor_sync(0xFFFFFFFFu, ssl[mt], o);
                ssh[mt] += __shfl_xor_sync(0xFFFFFFFFu, ssh[mt], o);
            }
        }
        if (tig == 0) {
            #pragma unroll
            for (int mt = 0; mt < 2; mt++) {
                atomicAdd(&s_ss[wm * 32 + mt * 16 + grp], ssl[mt]);
                atomicAdd(&s_ss[wm * 32 + mt * 16 + grp + 8], ssh[mt]);
            }
        }
        __syncthreads();
        #pragma unroll
        for (int mt = 0; mt < 2; mt++) {
            int lr = wm * 32 + mt * 16 + grp;
            int r_lo = row0 + lr, r_hi = r_lo + 8;
            float invlo = 1.0f / fmaxf(sqrtf(s_ss[lr]), L2_EPS);
            float invhi = 1.0f / fmaxf(sqrtf(s_ss[lr + 8]), L2_EPS);
            #pragma unroll
            for (int nt = 0; nt < 16; nt++) {
                int c = wn * 128 + nt * 8 + 2 * tig;
                if (r_lo < n_rows) {
                    float v0 = (acc[mt][nt][0] + s_shift[c]) * invlo;
                    float v1 = (acc[mt][nt][1] + s_shift[c + 1]) * invlo;
                    *(float2*)(outp + (size_t)r_lo * 256 + c) = make_float2(v0, v1);
                }
                if (r_hi < n_rows) {
                    float v2 = (acc[mt][nt][2] + s_shift[c]) * invhi;
                    float v3 = (acc[mt][nt][3] + s_shift[c + 1]) * invhi;
                    *(float2*)(outp + (size_t)r_hi * 256 + c) = make_float2(v2, v3);
                }
            }
        }
    }
}

// ---------------- launch ----------------
extern "C" void kernel_launch(void* const* d_in, const int* in_sizes, int n_in,
                              void* d_out, int out_size) {
    const float* x      = (const float*)d_in[0];
    const void*  ei     = d_in[1];
    const float* W1_l   = (const float*)d_in[2];
    const float* b1_l   = (const float*)d_in[3];
    const float* W1_r   = (const float*)d_in[4];
    const float* gamma  = (const float*)d_in[5];
    const float* beta   = (const float*)d_in[6];
    const float* mu     = (const float*)d_in[7];
    const float* var    = (const float*)d_in[8];
    const float* W2_l   = (const float*)d_in[9];
    const float* b2_l   = (const float*)d_in[10];
    const float* W2_r   = (const float*)d_in[11];
    float* out = (float*)d_out;

    const int N = in_sizes[0] / F_IN;     // 100000
    const int E = in_sizes[1] / 2;        // 800000
    const int nsb = (N + 1023) / 1024;

    static cudaStream_t s2 = nullptr;
    static cudaEvent_t evFork = nullptr, evJoin = nullptr;
    if (s2 == nullptr) {
        cudaStreamCreateWithFlags(&s2, cudaStreamNonBlocking);
        cudaEventCreateWithFlags(&evFork, cudaEventDisableTiming);
        cudaEventCreateWithFlags(&evJoin, cudaEventDisableTiming);
        cudaFuncSetAttribute(mma_gemm_kernel<1>, cudaFuncAttributeMaxDynamicSharedMemorySize, SMEM_MMA);
        cudaFuncSetAttribute(mma_gemm_kernel<2>, cudaFuncAttributeMaxDynamicSharedMemorySize, SMEM_MMA);
    }

    // fork: detect on main stream, then CSR chain on s2 while setup runs on main
    detect_kernel<<<1, 128>>>((const int*)ei);
    cudaEventRecord(evFork, 0);
    cudaStreamWaitEvent(s2, evFork, 0);

    // s2: CSR build
    zero_kernel<<<(N + 255) / 256, 256, 0, s2>>>();
    degree_kernel<<<(E + 255) / 256, 256, 0, s2>>>(ei, E);
    scan1_kernel<<<nsb, 1024, 0, s2>>>(N);
    scan2_kernel<<<1, 128, 0, s2>>>(nsb);
    scan3_kernel<<<nsb, 1024, 0, s2>>>(N, E);
    fill_kernel<<<(E + 255) / 256, 256, 0, s2>>>(ei, E);
    cudaEventRecord(evJoin, s2);

    // main: weight/x fp16 conversion (independent of CSR)
    setup_kernel<<<512, 256>>>(W1_l, W1_r, W2_l, W2_r, x, N);

    // join
    cudaStreamWaitEvent(0, evJoin, 0);

    // layer-1: A1 = [mean(x nbrs) | x]  (fp16)
    gather1_kernel<<<(N * 32 + 255) / 256, 256>>>(N);

    // h1 = relu(BN(A1 @ B1)) -> g_h1h fp16
    {
        int tiles = (N + 127) / 128;
        mma_gemm_kernel<1><<<tiles, 256, SMEM_MMA>>>(b1_l, gamma, beta, mu, var, nullptr, N);
    }

    // layer-2: A2 = mean(h1 nbrs)  (agg only; self read from g_h1h in GEMM)
    gather2_kernel<<<(N * 32 + 255) / 256, 256>>>(N);

    // out = l2norm([A2 | h1] @ B2 + b2)
    {
        int tiles = (N + 127) / 128;
        mma_gemm_kernel<2><<<tiles, 256, SMEM_MMA>>>(b2_l, nullptr, nullptr, nullptr, nullptr, out, N);
    }
}